// round 4
// baseline (speedup 1.0000x reference)
#include <cuda_runtime.h>
#include <cuda_bf16.h>
#include <math.h>
#include <stdint.h>

#define L_SEQ 1024
#define DM 768
#define DI 1536
#define DSTATE 16
#define DCONV 4
#define DTRANK 48
#define NLAYER 4
#define VOCAB 50280
#define VOCAB_PAD 50304            // 393*128
#define DBL_W (DTRANK + 2*DSTATE)  // 80

// ---------------- scratch (device globals) ---------------------------------
__device__ float g_h [L_SEQ*DM];
__device__ float g_hn[L_SEQ*DM];
__device__ float g_xz[L_SEQ*2*DI];
__device__ float g_xc[L_SEQ*DI];
__device__ float g_dbl[L_SEQ*DBL_W];
__device__ float g_dt[L_SEQ*DI];
__device__ float g_y [L_SEQ*DI];

// bf16x3 split buffers (K-concatenated: A'=[Ah|Al|Ah], B'=[Bh|Bh|Bl])
__device__ __nv_bfloat16 g_emb_s [(size_t)VOCAB_PAD * 3 * DM];
__device__ __nv_bfloat16 g_hn_s  [(size_t)L_SEQ     * 3 * DM];
__device__ __nv_bfloat16 g_inw_s [(size_t)2*DI      * 3 * DM];
__device__ __nv_bfloat16 g_y_s   [(size_t)L_SEQ     * 3 * DI];
__device__ __nv_bfloat16 g_outw_s[(size_t)DM        * 3 * DI];

__device__ __forceinline__ uint32_t s2u(const void* p){
    uint32_t a;
    asm("{ .reg .u64 t; cvta.to.shared.u64 t, %1; cvt.u32.u64 %0, t; }"
        : "=r"(a) : "l"(p));
    return a;
}

// ---------------- embedding gather ----------------------------------------
__global__ void embed_kernel(const int* __restrict__ ids,
                             const float* __restrict__ emb)
{
    int l = blockIdx.x;
    int id = ids[l];
    const float4* src = (const float4*)(emb + (size_t)id * DM);
    float4* dst = (float4*)(g_h + (size_t)l * DM);
    dst[threadIdx.x] = src[threadIdx.x];
}

// ---------------- rmsnorm --------------------------------------------------
__global__ void rmsnorm_kernel(const float* __restrict__ in,
                               float* __restrict__ out,
                               const float* __restrict__ w)
{
    int l = blockIdx.x;
    const float* x = in + (size_t)l * DM;
    float ss = 0.f;
    for (int i = threadIdx.x; i < DM; i += 256) {
        float v = x[i];
        ss = fmaf(v, v, ss);
    }
    #pragma unroll
    for (int off = 16; off >= 1; off >>= 1)
        ss += __shfl_xor_sync(0xffffffffu, ss, off);

    __shared__ float red[8];
    __shared__ float scale_s;
    int warp = threadIdx.x >> 5, lane = threadIdx.x & 31;
    if (lane == 0) red[warp] = ss;
    __syncthreads();
    if (threadIdx.x == 0) {
        float t = 0.f;
        #pragma unroll
        for (int i = 0; i < 8; i++) t += red[i];
        scale_s = rsqrtf(t / (float)DM + 1e-5f);
    }
    __syncthreads();
    float scale = scale_s;
    for (int i = threadIdx.x; i < DM; i += 256)
        out[(size_t)l * DM + i] = x[i] * scale * w[i];
}

// ---------------- bf16x3 split conversion ----------------------------------
__global__ void split3_kernel(const float* __restrict__ src,
                              __nv_bfloat16* __restrict__ dst,
                              int R, int K, int Rpad, int lo_seg)
{
    long long idx = (long long)blockIdx.x * blockDim.x + threadIdx.x;
    if (idx >= (long long)Rpad * K) return;
    int r = (int)(idx / K);
    int k = (int)(idx - (long long)r * K);
    float v = (r < R) ? src[(size_t)r * K + k] : 0.f;
    __nv_bfloat16 h = __float2bfloat16(v);
    __nv_bfloat16 l = __float2bfloat16(v - __bfloat162float(h));
    __nv_bfloat16* row = dst + (size_t)r * 3 * K;
    row[k]         = h;
    row[K + k]     = (lo_seg == 1) ? l : h;
    row[2 * K + k] = (lo_seg == 2) ? l : h;
}

// ---------------- depthwise causal conv (k=4) + bias + silu ----------------
__global__ void conv_silu_kernel(const float* __restrict__ cw,
                                 const float* __restrict__ cb)
{
    int idx = blockIdx.x * blockDim.x + threadIdx.x;
    int l = idx / DI;
    int d = idx - l * DI;
    float4 wv = *(const float4*)(cw + (size_t)d * 4);
    float acc = cb[d];
    const float* wj = (const float*)&wv;
    #pragma unroll
    for (int j = 0; j < DCONV; j++) {
        int ll = l - (DCONV - 1) + j;
        if (ll >= 0) acc = fmaf(wj[j], g_xz[(size_t)ll * 2 * DI + d], acc);
    }
    acc = acc / (1.f + __expf(-acc));
    g_xc[idx] = acc;
}

// ---------------- selective scan -------------------------------------------
__global__ void scan_kernel(const float* __restrict__ A_log)
{
    int gw   = (blockIdx.x * blockDim.x + threadIdx.x) >> 5;
    int lane = threadIdx.x & 31;
    int n    = lane & 15;
    int ch   = gw * 2 + (lane >> 4);

    float Aval = -__expf(A_log[(size_t)ch * DSTATE + n]);
    float s = 0.f;
    for (int l = 0; l < L_SEQ; l++) {
        float dtv = g_dt [(size_t)l * DI + ch];
        float xcv = g_xc [(size_t)l * DI + ch];
        float Bv  = g_dbl[(size_t)l * DBL_W + DTRANK + n];
        float Cv  = g_dbl[(size_t)l * DBL_W + DTRANK + DSTATE + n];
        s = __expf(dtv * Aval) * s + dtv * Bv * xcv;
        float p = s * Cv;
        p += __shfl_xor_sync(0xffffffffu, p, 1);
        p += __shfl_xor_sync(0xffffffffu, p, 2);
        p += __shfl_xor_sync(0xffffffffu, p, 4);
        p += __shfl_xor_sync(0xffffffffu, p, 8);
        if (n == 0) g_y[(size_t)l * DI + ch] = p;
    }
}

// ---------------- y = (y + xc*D) * silu(z) ---------------------------------
__global__ void y_epi_kernel(const float* __restrict__ Dp)
{
    int idx = blockIdx.x * blockDim.x + threadIdx.x;
    int l = idx / DI;
    int d = idx - l * DI;
    float z  = g_xz[(size_t)l * 2 * DI + DI + d];
    float yv = g_y[idx] + g_xc[idx] * Dp[d];
    yv *= z / (1.f + __expf(-z));
    g_y[idx] = yv;
}

// ---------------- fp32 TN GEMM (small shapes only) -------------------------
#define GBM 128
#define GBN 64
#define GBK 16

template<int EPI>
__global__ __launch_bounds__(256)
void gemm_tn(const float* __restrict__ A, int lda,
             const float* __restrict__ B, int ldb,
             float* __restrict__ C, int ldc,
             int N, int K, const float* __restrict__ bias)
{
    __shared__ float As[GBK][GBM + 4];
    __shared__ float Bs[GBK][GBN + 4];

    const int bm  = blockIdx.y * GBM;
    const int bn  = blockIdx.x * GBN;
    const int tid = threadIdx.x;
    const int tx  = tid & 15;
    const int ty  = tid >> 4;
    const int a_row = tid >> 1;
    const int a_k   = (tid & 1) * 8;
    const int b_row = tid >> 2;
    const int b_k   = (tid & 3) * 4;

    float acc[8][4];
    #pragma unroll
    for (int i = 0; i < 8; i++)
        #pragma unroll
        for (int j = 0; j < 4; j++) acc[i][j] = 0.f;

    const float* Aptr = A + (size_t)(bm + a_row) * lda + a_k;
    const int gbn = bn + b_row;
    const float* Bptr = (gbn < N) ? (B + (size_t)gbn * ldb + b_k) : 0;

    for (int k0 = 0; k0 < K; k0 += GBK) {
        float4 av0 = *(const float4*)(Aptr + k0);
        float4 av1 = *(const float4*)(Aptr + k0 + 4);
        float4 bv  = Bptr ? *(const float4*)(Bptr + k0)
                          : make_float4(0.f, 0.f, 0.f, 0.f);

        As[a_k + 0][a_row] = av0.x; As[a_k + 1][a_row] = av0.y;
        As[a_k + 2][a_row] = av0.z; As[a_k + 3][a_row] = av0.w;
        As[a_k + 4][a_row] = av1.x; As[a_k + 5][a_row] = av1.y;
        As[a_k + 6][a_row] = av1.z; As[a_k + 7][a_row] = av1.w;
        Bs[b_k + 0][b_row] = bv.x;  Bs[b_k + 1][b_row] = bv.y;
        Bs[b_k + 2][b_row] = bv.z;  Bs[b_k + 3][b_row] = bv.w;
        __syncthreads();

        #pragma unroll
        for (int kk = 0; kk < GBK; kk++) {
            float ar[8], br[4];
            #pragma unroll
            for (int i = 0; i < 8; i++) ar[i] = As[kk][ty * 8 + i];
            #pragma unroll
            for (int j = 0; j < 4; j++) br[j] = Bs[kk][tx * 4 + j];
            #pragma unroll
            for (int i = 0; i < 8; i++)
                #pragma unroll
                for (int j = 0; j < 4; j++)
                    acc[i][j] = fmaf(ar[i], br[j], acc[i][j]);
        }
        __syncthreads();
    }

    #pragma unroll
    for (int i = 0; i < 8; i++) {
        int m = bm + ty * 8 + i;
        #pragma unroll
        for (int j = 0; j < 4; j++) {
            int n = bn + tx * 4 + j;
            if (n < N) {
                float v = acc[i][j];
                if (EPI == 1) {
                    v += bias[n];
                    v = fmaxf(v, 0.f) + log1pf(__expf(-fabsf(v)));
                }
                if (EPI == 2) C[(size_t)m * ldc + n] += v;
                else          C[(size_t)m * ldc + n] = v;
            }
        }
    }
}

// ---------------- bf16 HMMA GEMM (mma.sync m16n8k16) -----------------------
// C[m][n] = sum_k A'[m][k]*B'[n][k].  CTA tile 128x128, BK=32, 8 warps (2x4),
// warp tile 64x32. Double-buffered smem via cp.async. fp32 accumulate.
#define TCM 128
#define TCN 128
#define TCK 32
// smem row = 32 bf16 = 64B = 4 x 16B chunks; chunk swizzle: c ^= (row & 3)

__device__ __forceinline__ void cp_async16(uint32_t s, const void* g)
{
    asm volatile("cp.async.cg.shared.global [%0], [%1], 16;\n"
                 :: "r"(s), "l"(g));
}
__device__ __forceinline__ void cp_commit(){ asm volatile("cp.async.commit_group;\n" ::: "memory"); }
template<int N> __device__ __forceinline__ void cp_wait(){ asm volatile("cp.async.wait_group %0;\n" :: "n"(N) : "memory"); }

__device__ __forceinline__ void ldsm_x4(uint32_t* r, uint32_t addr)
{
    asm volatile("ldmatrix.sync.aligned.m8n8.x4.shared.b16 {%0,%1,%2,%3}, [%4];"
                 : "=r"(r[0]), "=r"(r[1]), "=r"(r[2]), "=r"(r[3]) : "r"(addr));
}
__device__ __forceinline__ void mma16816(float* c, const uint32_t* a, const uint32_t* b)
{
    asm volatile(
        "mma.sync.aligned.m16n8k16.row.col.f32.bf16.bf16.f32 "
        "{%0,%1,%2,%3}, {%4,%5,%6,%7}, {%8,%9}, {%0,%1,%2,%3};"
        : "+f"(c[0]), "+f"(c[1]), "+f"(c[2]), "+f"(c[3])
        : "r"(a[0]), "r"(a[1]), "r"(a[2]), "r"(a[3]), "r"(b[0]), "r"(b[1]));
}

template<int EPI>
__global__ __launch_bounds__(256)
void mma_gemm(const __nv_bfloat16* __restrict__ A,
              const __nv_bfloat16* __restrict__ B,
              float* __restrict__ C, int ldc, int N, int Kp)
{
    __shared__ __align__(16) char sm[2 * (TCM * 64 + TCN * 64)];  // 32 KB
    const uint32_t sbase = s2u(sm);
    const int tid  = threadIdx.x;
    const int wid  = tid >> 5, lane = tid & 31;
    const int wm   = wid & 1;          // 0..1 -> 64-row block
    const int wn   = wid >> 1;         // 0..3 -> 32-col block
    const int bm   = blockIdx.y * TCM;
    const int bn   = blockIdx.x * TCN;

    const int chunks = Kp / TCK;

    // cp.async: each thread loads 2 A vecs + 2 B vecs / stage
    const int v0 = tid, v1 = tid + 256;
    const int ar0 = v0 >> 2, ak0 = v0 & 3;
    const int ar1 = v1 >> 2, ak1 = v1 & 3;
    const __nv_bfloat16* Ag0 = A + (size_t)(bm + ar0) * Kp + ak0 * 8;
    const __nv_bfloat16* Ag1 = A + (size_t)(bm + ar1) * Kp + ak1 * 8;
    const __nv_bfloat16* Bg0 = B + (size_t)(bn + ar0) * Kp + ak0 * 8;
    const __nv_bfloat16* Bg1 = B + (size_t)(bn + ar1) * Kp + ak1 * 8;
    const uint32_t sa0 = sbase + ar0 * 64 + ((ak0 ^ (ar0 & 3)) * 16);
    const uint32_t sa1 = sbase + ar1 * 64 + ((ak1 ^ (ar1 & 3)) * 16);
    const uint32_t sb0 = sbase + TCM * 64 + ar0 * 64 + ((ak0 ^ (ar0 & 3)) * 16);
    const uint32_t sb1 = sbase + TCM * 64 + ar1 * 64 + ((ak1 ^ (ar1 & 3)) * 16);
    const uint32_t stage_sz = TCM * 64 + TCN * 64;

    float acc[4][4][4];
    #pragma unroll
    for (int i = 0; i < 4; i++)
        #pragma unroll
        for (int j = 0; j < 4; j++)
            #pragma unroll
            for (int t = 0; t < 4; t++) acc[i][j][t] = 0.f;

    // A (row-major [m][k]): lanes 0-15 -> rows m0-15 @k-chunk 0, lanes 16-31 -> +16B
    const int a_row = wm * 64 + (lane & 15);
    const int a_k8s = lane >> 4;                     // 0/1
    // B ([n][k], plain ldmatrix): lanes 0-7 n0-7@k0, 8-15 n0-7@k8, 16-23 n8-15@k0, 24-31 n8-15@k8
    const int b_row = wn * 32 + (lane & 7) + ((lane >> 4) << 3);
    const int b_k8s = (lane >> 3) & 1;

    // prologue: stage 0
    {
        cp_async16(sa0, Ag0); cp_async16(sa1, Ag1);
        cp_async16(sb0, Bg0); cp_async16(sb1, Bg1);
        cp_commit();
    }

    for (int c = 0; c < chunks; c++) {
        const int buf = c & 1;
        if (c + 1 < chunks) {
            const int nbuf = (c + 1) & 1;
            const uint32_t so = nbuf * stage_sz;
            const int ko = (c + 1) * TCK;
            cp_async16(sa0 + so, Ag0 + ko); cp_async16(sa1 + so, Ag1 + ko);
            cp_async16(sb0 + so, Bg0 + ko); cp_async16(sb1 + so, Bg1 + ko);
            cp_commit();
            cp_wait<1>();
        } else {
            cp_wait<0>();
        }
        __syncthreads();

        const uint32_t sA = sbase + buf * stage_sz;
        const uint32_t sB = sA + TCM * 64;

        #pragma unroll
        for (int k16 = 0; k16 < 2; k16++) {
            uint32_t afrag[4][4];
            #pragma unroll
            for (int mt = 0; mt < 4; mt++) {
                int row = a_row + mt * 16;
                int k8 = k16 * 2 + a_k8s;
                ldsm_x4(afrag[mt], sA + row * 64 + ((k8 ^ (row & 3)) * 16));
            }
            uint32_t bfrag[4][2];
            #pragma unroll
            for (int np = 0; np < 2; np++) {
                int row = b_row + np * 16;
                int k8 = k16 * 2 + b_k8s;
                uint32_t t[4];
                ldsm_x4(t, sB + row * 64 + ((k8 ^ (row & 3)) * 16));
                bfrag[np * 2 + 0][0] = t[0]; bfrag[np * 2 + 0][1] = t[1];
                bfrag[np * 2 + 1][0] = t[2]; bfrag[np * 2 + 1][1] = t[3];
            }
            #pragma unroll
            for (int mt = 0; mt < 4; mt++)
                #pragma unroll
                for (int nt = 0; nt < 4; nt++)
                    mma16816(acc[mt][nt], afrag[mt], bfrag[nt]);
        }
        __syncthreads();
    }

    // epilogue
    const int erow = lane >> 2;
    const int ecol = (lane & 3) * 2;
    #pragma unroll
    for (int mt = 0; mt < 4; mt++) {
        #pragma unroll
        for (int nt = 0; nt < 4; nt++) {
            int m0 = bm + wm * 64 + mt * 16 + erow;
            int n0 = bn + wn * 32 + nt * 8 + ecol;
            float* p0 = C + (size_t)m0 * ldc + n0;
            float* p1 = p0 + 8 * ldc;
            if (n0 < N) {
                float2 v0 = make_float2(acc[mt][nt][0], acc[mt][nt][1]);
                float2 v1 = make_float2(acc[mt][nt][2], acc[mt][nt][3]);
                if (EPI == 2) {
                    float2 o0 = *(float2*)p0, o1 = *(float2*)p1;
                    v0.x += o0.x; v0.y += o0.y; v1.x += o1.x; v1.y += o1.y;
                }
                *(float2*)p0 = v0;
                *(float2*)p1 = v1;
            }
        }
    }
}

// ---------------- orchestration --------------------------------------------
extern "C" void kernel_launch(void* const* d_in, const int* in_sizes, int n_in,
                              void* d_out, int out_size)
{
    const int*   ids        = (const int*)  d_in[0];
    const float* emb        = (const float*)d_in[1];
    const float* in_proj_w  = (const float*)d_in[2];
    const float* conv_w     = (const float*)d_in[3];
    const float* conv_b     = (const float*)d_in[4];
    const float* x_proj_w   = (const float*)d_in[5];
    const float* dt_proj_w  = (const float*)d_in[6];
    const float* dt_proj_b  = (const float*)d_in[7];
    const float* A_log      = (const float*)d_in[8];
    const float* D_param    = (const float*)d_in[9];
    const float* out_proj_w = (const float*)d_in[10];
    const float* norm_w     = (const float*)d_in[11];
    const float* norm_f_w   = (const float*)d_in[12];
    float* logits = (float*)d_out;

    float *h, *hn, *xz, *xc, *dbl, *dt, *y;
    cudaGetSymbolAddress((void**)&h,   g_h);
    cudaGetSymbolAddress((void**)&hn,  g_hn);
    cudaGetSymbolAddress((void**)&xz,  g_xz);
    cudaGetSymbolAddress((void**)&xc,  g_xc);
    cudaGetSymbolAddress((void**)&dbl, g_dbl);
    cudaGetSymbolAddress((void**)&dt,  g_dt);
    cudaGetSymbolAddress((void**)&y,   g_y);

    __nv_bfloat16 *emb_s, *hn_s, *inw_s, *y_s, *outw_s;
    cudaGetSymbolAddress((void**)&emb_s,  g_emb_s);
    cudaGetSymbolAddress((void**)&hn_s,   g_hn_s);
    cudaGetSymbolAddress((void**)&inw_s,  g_inw_s);
    cudaGetSymbolAddress((void**)&y_s,    g_y_s);
    cudaGetSymbolAddress((void**)&outw_s, g_outw_s);

    embed_kernel<<<L_SEQ, DM / 4>>>(ids, emb);

    // embedding split (B-side: lo in segment 2) — for the final logits GEMM
    {
        long long tot = (long long)VOCAB_PAD * DM;
        split3_kernel<<<(unsigned)((tot + 255) / 256), 256>>>(emb, emb_s, VOCAB, DM, VOCAB_PAD, 2);
    }

    for (int i = 0; i < NLAYER; i++) {
        rmsnorm_kernel<<<L_SEQ, 256>>>(h, hn, norm_w + (size_t)i * DM);

        split3_kernel<<<(L_SEQ * DM) / 256, 256>>>(hn, hn_s, L_SEQ, DM, L_SEQ, 1);
        split3_kernel<<<(2 * DI * DM) / 256, 256>>>(in_proj_w + (size_t)i * 2 * DI * DM,
                                                    inw_s, 2 * DI, DM, 2 * DI, 2);

        // xz = hn @ in_proj_w^T   (1024 x 3072, K'=2304)
        {
            dim3 g1(2 * DI / TCN, L_SEQ / TCM);
            mma_gemm<0><<<g1, 256>>>(hn_s, inw_s, xz, 2 * DI, 2 * DI, 3 * DM);
        }

        conv_silu_kernel<<<(L_SEQ * DI) / 256, 256>>>(
            conv_w + (size_t)i * DI * DCONV, conv_b + (size_t)i * DI);

        // dbl = xc @ x_proj_w^T   (1024 x 80, K=1536)  — small, fp32
        {
            dim3 g2((DBL_W + GBN - 1) / GBN, L_SEQ / GBM);
            gemm_tn<0><<<g2, 256>>>(xc, DI,
                                    x_proj_w + (size_t)i * DBL_W * DI, DI,
                                    dbl, DBL_W, DBL_W, DI, 0);
        }

        // dt = softplus(dbl[:, :48] @ dt_proj_w^T + b)  (1024 x 1536, K=48)
        {
            dim3 g3((DI + GBN - 1) / GBN, L_SEQ / GBM);
            gemm_tn<1><<<g3, 256>>>(dbl, DBL_W,
                                    dt_proj_w + (size_t)i * DI * DTRANK, DTRANK,
                                    dt, DI, DI, DTRANK,
                                    dt_proj_b + (size_t)i * DI);
        }

        scan_kernel<<<DI / 8, 128>>>(A_log + (size_t)i * DI * DSTATE);

        y_epi_kernel<<<(L_SEQ * DI) / 256, 256>>>(D_param + (size_t)i * DI);

        split3_kernel<<<(L_SEQ * DI) / 256, 256>>>(y, y_s, L_SEQ, DI, L_SEQ, 1);
        split3_kernel<<<(DM * DI) / 256, 256>>>(out_proj_w + (size_t)i * DM * DI,
                                                outw_s, DM, DI, DM, 2);

        // h += y @ out_proj_w^T   (1024 x 768, K'=4608)
        {
            dim3 g4(DM / TCN, L_SEQ / TCM);
            mma_gemm<2><<<g4, 256>>>(y_s, outw_s, h, DM, DM, 3 * DI);
        }
    }

    rmsnorm_kernel<<<L_SEQ, 256>>>(h, hn, norm_f_w);
    split3_kernel<<<(L_SEQ * DM) / 256, 256>>>(hn, hn_s, L_SEQ, DM, L_SEQ, 1);

    // logits = hn @ emb^T   (1024 x 50280, K'=2304) — dominant GEMM
    {
        dim3 g5(VOCAB_PAD / TCN, L_SEQ / TCM);
        mma_gemm<0><<<g5, 256>>>(hn_s, emb_s, logits, VOCAB, VOCAB, 3 * DM);
    }
}